// round 2
// baseline (speedup 1.0000x reference)
#include <cuda_runtime.h>

// Blur_by_Kernel: per-batch 21x21 cross-correlation, reflect pad 10.
// input  (16,3,768,768) fp32, kernel (16,21,21) fp32.
// out[b,c,y,x] = sum_{ky,kx} in[b,c, refl(y+ky-10), refl(x+kx-10)] * w[b,ky,kx]
//
// R2 design: packed f32x2 FFMA (2 MAC/lane/instr) + row-sliding smem windows.
//  - thread tile: 8 cols x 3 rows; block 16x16 threads -> 128x48 outputs
//  - per smem-row window (28 floats): reused by up to 3 output rows (ky = s-r)
//  - weights pre-duplicated as (w,w) u64 pairs in smem -> LDS.64 broadcast
//  - kx loop split by parity: even kx uses aligned pairs A[14], odd uses
//    shifted pairs S[13]; all FFMA2 operands are 64-bit register pairs.

typedef unsigned long long u64;

namespace {
constexpr int HW   = 768;
constexpr int KS   = 21;
constexpr int PAD  = 10;
constexpr int CPT  = 8;                 // cols per thread
constexpr int RPT  = 3;                 // rows per thread
constexpr int TXN  = 16, TYN = 16;
constexpr int TILE_X = CPT * TXN;       // 128
constexpr int TILE_Y = RPT * TYN;       // 48
constexpr int SM_W = TILE_X + 2 * PAD;  // 148 floats/row (592B, 16B aligned)
constexpr int SM_H = TILE_Y + 2 * PAD;  // 68 rows
constexpr int NT   = TXN * TYN;         // 256
}

__device__ __forceinline__ u64 pack2(float lo, float hi) {
    u64 r;
    asm("mov.b64 %0, {%1, %2};" : "=l"(r) : "f"(lo), "f"(hi));
    return r;
}
// d.lo += a.lo*b.lo ; d.hi += a.hi*b.hi   (packed fp32x2 FMA)
__device__ __forceinline__ void ffma2(u64 &d, u64 a, u64 b) {
    asm("fma.rn.f32x2 %0, %1, %2, %0;" : "+l"(d) : "l"(a), "l"(b));
}

template <int RI>
__device__ __forceinline__ void pass_even(u64 (&acc)[RPT][4],
                                          const u64* __restrict__ wr,
                                          const u64 (&A)[14]) {
    #pragma unroll
    for (int kx = 0; kx < KS; kx += 2) {
        u64 wp = wr[kx];                       // broadcast LDS.64, pair (w,w)
        #pragma unroll
        for (int j = 0; j < 4; ++j)
            ffma2(acc[RI][j], A[(kx >> 1) + j], wp);
    }
}

template <int RI>
__device__ __forceinline__ void pass_odd(u64 (&acc)[RPT][4],
                                         const u64* __restrict__ wr,
                                         const u64 (&S)[13]) {
    #pragma unroll
    for (int kx = 1; kx < KS; kx += 2) {
        u64 wp = wr[kx];
        #pragma unroll
        for (int j = 0; j < 4; ++j)
            ffma2(acc[RI][j], S[(kx >> 1) + j], wp);
    }
}

__global__ __launch_bounds__(NT, 2)
void blur21_kernel(const float* __restrict__ in,
                   const float* __restrict__ wts,
                   float* __restrict__ out)
{
    __shared__ float tile[SM_H][SM_W];
    __shared__ u64   swp[KS * KS];

    const int bc  = blockIdx.z;          // b*3 + c
    const int b   = bc / 3;
    const int bx  = blockIdx.x * TILE_X;
    const int by  = blockIdx.y * TILE_Y;
    const int tid = threadIdx.x;

    const float* __restrict__ img = in + (size_t)bc * (HW * HW);

    // duplicated weight pairs (w,w) for this batch
    for (int i = tid; i < KS * KS; i += NT) {
        float w = wts[b * (KS * KS) + i];
        swp[i] = pack2(w, w);
    }

    // input tile with reflect indexing (pad < HW -> single reflection)
    for (int i = tid; i < SM_H * SM_W; i += NT) {
        int r  = i / SM_W;
        int c  = i - r * SM_W;
        int gy = by + r - PAD;
        int gx = bx + c - PAD;
        gy = (gy < 0) ? -gy : ((gy >= HW) ? (2 * HW - 2 - gy) : gy);
        gx = (gx < 0) ? -gx : ((gx >= HW) ? (2 * HW - 2 - gx) : gx);
        tile[r][c] = img[gy * HW + gx];
    }
    __syncthreads();

    const int tx = tid & 15;
    const int ty = tid >> 4;
    const int ox = tx * CPT;             // tile-local col base (32B aligned)
    const int oy = ty * RPT;             // tile-local row base

    u64 acc[RPT][4];
    #pragma unroll
    for (int r = 0; r < RPT; ++r)
        #pragma unroll
        for (int j = 0; j < 4; ++j)
            acc[r][j] = 0ull;

    // slide over the 23 tile rows this thread's outputs depend on;
    // window row s feeds output row r (=0..2) with weight row ky = s - r.
    #pragma unroll 1
    for (int s = 0; s < RPT + KS - 1; ++s) {
        float4 q[7];
        const float4* __restrict__ rp = (const float4*)&tile[oy + s][ox];
        #pragma unroll
        for (int i = 0; i < 7; ++i) q[i] = rp[i];

        // aligned pairs A[j] = (v[2j], v[2j+1])
        u64 A[14];
        #pragma unroll
        for (int i = 0; i < 7; ++i) {
            A[2 * i]     = pack2(q[i].x, q[i].y);
            A[2 * i + 1] = pack2(q[i].z, q[i].w);
        }
        if (s <= KS - 1) pass_even<0>(acc, &swp[s * KS], A);
        if (s >= 1 && s <= KS) pass_even<1>(acc, &swp[(s - 1) * KS], A);
        if (s >= 2) pass_even<2>(acc, &swp[(s - 2) * KS], A);

        // shifted pairs S[j] = (v[2j+1], v[2j+2])
        u64 S[13];
        #pragma unroll
        for (int i = 0; i < 6; ++i) {
            S[2 * i]     = pack2(q[i].y, q[i].z);
            S[2 * i + 1] = pack2(q[i].w, q[i + 1].x);
        }
        S[12] = pack2(q[6].y, q[6].z);

        if (s <= KS - 1) pass_odd<0>(acc, &swp[s * KS], S);
        if (s >= 1 && s <= KS) pass_odd<1>(acc, &swp[(s - 1) * KS], S);
        if (s >= 2) pass_odd<2>(acc, &swp[(s - 2) * KS], S);
    }

    // store: 3 rows x 4 u64 (8 floats) per thread, 8B-aligned
    float* __restrict__ o = out + (size_t)bc * (HW * HW)
                                + (size_t)(by + oy) * HW + (bx + ox);
    #pragma unroll
    for (int r = 0; r < RPT; ++r) {
        u64* __restrict__ op = (u64*)(o + (size_t)r * HW);
        #pragma unroll
        for (int j = 0; j < 4; ++j) op[j] = acc[r][j];
    }
}

extern "C" void kernel_launch(void* const* d_in, const int* in_sizes, int n_in,
                              void* d_out, int out_size)
{
    const float* img = (const float*)d_in[0];
    const float* wts = (const float*)d_in[1];
    if (n_in >= 2 && in_sizes[0] == 16 * KS * KS) {   // 7056 -> kernel tensor
        img = (const float*)d_in[1];
        wts = (const float*)d_in[0];
    }

    dim3 grid(HW / TILE_X, HW / TILE_Y, 16 * 3);
    blur21_kernel<<<grid, NT>>>(img, wts, (float*)d_out);
}

// round 3
// speedup vs baseline: 1.4831x; 1.4831x over previous
#include <cuda_runtime.h>

// Blur_by_Kernel: per-batch 21x21 cross-correlation, reflect pad 10.
// input (16,3,768,768) fp32, kernel (16,21,21) fp32.
// out[b,c,y,x] = sum_{ky,kx} in[b,c, refl(y+ky-10), refl(x+kx-10)] * w[b,ky,kx]
//
// R3: scalar FFMA, row-sliding register windows (1 smem-row load reused by
// 3 output rows), branch-free interior via loop splitting, weight rows padded
// to 24 floats for LDS.128 broadcast. Crossbar ~46 cyc/window vs FMA 126 ->
// FMA-pipe bound by design.

namespace {
constexpr int HW   = 768;
constexpr int KS   = 21;
constexpr int PAD  = 10;
constexpr int CPT  = 8;                  // cols per thread
constexpr int RPT  = 3;                  // rows per thread
constexpr int TXN  = 16, TYN = 16;
constexpr int TILE_X = CPT * TXN;        // 128
constexpr int TILE_Y = RPT * TYN;        // 48
constexpr int SM_W = TILE_X + 2 * PAD;   // 148 floats (592B rows, 16B aligned)
constexpr int SM_H = TILE_Y + 2 * PAD;   // 68 rows
constexpr int WSTRIDE = 24;              // padded weight row (96B, 16B aligned)
constexpr int NT   = TXN * TYN;          // 256
}

// one weight-row pass: acc[j] += sum_kx v[kx+j] * w[kx]
__device__ __forceinline__ void do_pass(float (&acc)[CPT],
                                        const float* __restrict__ wr,
                                        const float (&v)[28])
{
    #pragma unroll
    for (int g = 0; g < 5; ++g) {
        const float4 w = *(const float4*)(wr + 4 * g);   // broadcast LDS.128
        #pragma unroll
        for (int j = 0; j < CPT; ++j) acc[j] = fmaf(v[4*g + 0 + j], w.x, acc[j]);
        #pragma unroll
        for (int j = 0; j < CPT; ++j) acc[j] = fmaf(v[4*g + 1 + j], w.y, acc[j]);
        #pragma unroll
        for (int j = 0; j < CPT; ++j) acc[j] = fmaf(v[4*g + 2 + j], w.z, acc[j]);
        #pragma unroll
        for (int j = 0; j < CPT; ++j) acc[j] = fmaf(v[4*g + 3 + j], w.w, acc[j]);
    }
    const float wl = wr[20];
    #pragma unroll
    for (int j = 0; j < CPT; ++j) acc[j] = fmaf(v[20 + j], wl, acc[j]);
}

__global__ __launch_bounds__(NT, 3)
void blur21_kernel(const float* __restrict__ in,
                   const float* __restrict__ wts,
                   float* __restrict__ out)
{
    __shared__ float tile[SM_H][SM_W];
    __shared__ float sw[KS * WSTRIDE];

    const int bc  = blockIdx.z;           // b*3 + c
    const int b   = bc / 3;
    const int bx  = blockIdx.x * TILE_X;
    const int by  = blockIdx.y * TILE_Y;
    const int tid = threadIdx.x;

    const float* __restrict__ img = in + (size_t)bc * (HW * HW);

    // weights for this batch, rows padded to WSTRIDE
    for (int i = tid; i < KS * WSTRIDE; i += NT) {
        const int r = i / WSTRIDE, c = i - r * WSTRIDE;
        sw[i] = (c < KS) ? wts[b * (KS * KS) + r * KS + c] : 0.f;
    }

    // input tile with reflect indexing (pad < HW -> single reflection)
    for (int i = tid; i < SM_H * SM_W; i += NT) {
        const int r  = i / SM_W;
        const int c  = i - r * SM_W;
        int gy = by + r - PAD;
        int gx = bx + c - PAD;
        gy = (gy < 0) ? -gy : ((gy >= HW) ? (2 * HW - 2 - gy) : gy);
        gx = (gx < 0) ? -gx : ((gx >= HW) ? (2 * HW - 2 - gx) : gx);
        tile[r][c] = img[gy * HW + gx];
    }
    __syncthreads();

    const int tx = tid & 15;
    const int ty = tid >> 4;
    const int ox = tx * CPT;              // 32B-aligned smem col base
    const int oy = ty * RPT;

    float acc0[CPT], acc1[CPT], acc2[CPT];
    #pragma unroll
    for (int j = 0; j < CPT; ++j) { acc0[j] = 0.f; acc1[j] = 0.f; acc2[j] = 0.f; }

    float v[28];
    #define LOADW(s)                                                     \
        do {                                                             \
            const float4* __restrict__ p =                               \
                (const float4*)&tile[oy + (s)][ox];                      \
            _Pragma("unroll")                                            \
            for (int i = 0; i < 7; ++i) {                                \
                const float4 q = p[i];                                   \
                v[4*i+0] = q.x; v[4*i+1] = q.y;                          \
                v[4*i+2] = q.z; v[4*i+3] = q.w;                          \
            }                                                            \
        } while (0)

    // window row s feeds output row r with weight row (s - r)
    LOADW(0);
    do_pass(acc0, &sw[0 * WSTRIDE], v);

    LOADW(1);
    do_pass(acc0, &sw[1 * WSTRIDE], v);
    do_pass(acc1, &sw[0 * WSTRIDE], v);

    #pragma unroll 1
    for (int s = 2; s <= 20; ++s) {
        LOADW(s);
        const float* __restrict__ w0 = &sw[s * WSTRIDE];
        do_pass(acc0, w0, v);
        do_pass(acc1, w0 - WSTRIDE, v);
        do_pass(acc2, w0 - 2 * WSTRIDE, v);
    }

    LOADW(21);
    do_pass(acc1, &sw[20 * WSTRIDE], v);
    do_pass(acc2, &sw[19 * WSTRIDE], v);

    LOADW(22);
    do_pass(acc2, &sw[20 * WSTRIDE], v);

    #undef LOADW

    float* __restrict__ o = out + (size_t)bc * (HW * HW)
                                + (size_t)(by + oy) * HW + (bx + ox);
    *(float4*)(o)              = make_float4(acc0[0], acc0[1], acc0[2], acc0[3]);
    *(float4*)(o + 4)          = make_float4(acc0[4], acc0[5], acc0[6], acc0[7]);
    *(float4*)(o + HW)         = make_float4(acc1[0], acc1[1], acc1[2], acc1[3]);
    *(float4*)(o + HW + 4)     = make_float4(acc1[4], acc1[5], acc1[6], acc1[7]);
    *(float4*)(o + 2 * HW)     = make_float4(acc2[0], acc2[1], acc2[2], acc2[3]);
    *(float4*)(o + 2 * HW + 4) = make_float4(acc2[4], acc2[5], acc2[6], acc2[7]);
}

extern "C" void kernel_launch(void* const* d_in, const int* in_sizes, int n_in,
                              void* d_out, int out_size)
{
    const float* img = (const float*)d_in[0];
    const float* wts = (const float*)d_in[1];
    if (n_in >= 2 && in_sizes[0] == 16 * KS * KS) {   // 7056 -> kernel tensor
        img = (const float*)d_in[1];
        wts = (const float*)d_in[0];
    }

    dim3 grid(HW / TILE_X, HW / TILE_Y, 16 * 3);
    blur21_kernel<<<grid, NT>>>(img, wts, (float*)d_out);
}

// round 4
// speedup vs baseline: 1.4836x; 1.0004x over previous
#include <cuda_runtime.h>

// Blur_by_Kernel: per-batch 21x21 cross-correlation, reflect pad 10.
// input (16,3,768,768) fp32, kernel (16,21,21) fp32.
// out[b,c,y,x] = sum_{ky,kx} in[b,c, refl(y+ky-10), refl(x+kx-10)] * w[b,ky,kx]
//
// R3: scalar FFMA, row-sliding register windows (1 smem-row load reused by
// 3 output rows), branch-free interior via loop splitting, weight rows padded
// to 24 floats for LDS.128 broadcast. Crossbar ~46 cyc/window vs FMA 126 ->
// FMA-pipe bound by design.

namespace {
constexpr int HW   = 768;
constexpr int KS   = 21;
constexpr int PAD  = 10;
constexpr int CPT  = 8;                  // cols per thread
constexpr int RPT  = 3;                  // rows per thread
constexpr int TXN  = 16, TYN = 16;
constexpr int TILE_X = CPT * TXN;        // 128
constexpr int TILE_Y = RPT * TYN;        // 48
constexpr int SM_W = TILE_X + 2 * PAD;   // 148 floats (592B rows, 16B aligned)
constexpr int SM_H = TILE_Y + 2 * PAD;   // 68 rows
constexpr int WSTRIDE = 24;              // padded weight row (96B, 16B aligned)
constexpr int NT   = TXN * TYN;          // 256
}

// one weight-row pass: acc[j] += sum_kx v[kx+j] * w[kx]
__device__ __forceinline__ void do_pass(float (&acc)[CPT],
                                        const float* __restrict__ wr,
                                        const float (&v)[28])
{
    #pragma unroll
    for (int g = 0; g < 5; ++g) {
        const float4 w = *(const float4*)(wr + 4 * g);   // broadcast LDS.128
        #pragma unroll
        for (int j = 0; j < CPT; ++j) acc[j] = fmaf(v[4*g + 0 + j], w.x, acc[j]);
        #pragma unroll
        for (int j = 0; j < CPT; ++j) acc[j] = fmaf(v[4*g + 1 + j], w.y, acc[j]);
        #pragma unroll
        for (int j = 0; j < CPT; ++j) acc[j] = fmaf(v[4*g + 2 + j], w.z, acc[j]);
        #pragma unroll
        for (int j = 0; j < CPT; ++j) acc[j] = fmaf(v[4*g + 3 + j], w.w, acc[j]);
    }
    const float wl = wr[20];
    #pragma unroll
    for (int j = 0; j < CPT; ++j) acc[j] = fmaf(v[20 + j], wl, acc[j]);
}

__global__ __launch_bounds__(NT, 3)
void blur21_kernel(const float* __restrict__ in,
                   const float* __restrict__ wts,
                   float* __restrict__ out)
{
    __shared__ float tile[SM_H][SM_W];
    __shared__ float sw[KS * WSTRIDE];

    const int bc  = blockIdx.z;           // b*3 + c
    const int b   = bc / 3;
    const int bx  = blockIdx.x * TILE_X;
    const int by  = blockIdx.y * TILE_Y;
    const int tid = threadIdx.x;

    const float* __restrict__ img = in + (size_t)bc * (HW * HW);

    // weights for this batch, rows padded to WSTRIDE
    for (int i = tid; i < KS * WSTRIDE; i += NT) {
        const int r = i / WSTRIDE, c = i - r * WSTRIDE;
        sw[i] = (c < KS) ? wts[b * (KS * KS) + r * KS + c] : 0.f;
    }

    // input tile with reflect indexing (pad < HW -> single reflection)
    for (int i = tid; i < SM_H * SM_W; i += NT) {
        const int r  = i / SM_W;
        const int c  = i - r * SM_W;
        int gy = by + r - PAD;
        int gx = bx + c - PAD;
        gy = (gy < 0) ? -gy : ((gy >= HW) ? (2 * HW - 2 - gy) : gy);
        gx = (gx < 0) ? -gx : ((gx >= HW) ? (2 * HW - 2 - gx) : gx);
        tile[r][c] = img[gy * HW + gx];
    }
    __syncthreads();

    const int tx = tid & 15;
    const int ty = tid >> 4;
    const int ox = tx * CPT;              // 32B-aligned smem col base
    const int oy = ty * RPT;

    float acc0[CPT], acc1[CPT], acc2[CPT];
    #pragma unroll
    for (int j = 0; j < CPT; ++j) { acc0[j] = 0.f; acc1[j] = 0.f; acc2[j] = 0.f; }

    float v[28];
    #define LOADW(s)                                                     \
        do {                                                             \
            const float4* __restrict__ p =                               \
                (const float4*)&tile[oy + (s)][ox];                      \
            _Pragma("unroll")                                            \
            for (int i = 0; i < 7; ++i) {                                \
                const float4 q = p[i];                                   \
                v[4*i+0] = q.x; v[4*i+1] = q.y;                          \
                v[4*i+2] = q.z; v[4*i+3] = q.w;                          \
            }                                                            \
        } while (0)

    // window row s feeds output row r with weight row (s - r)
    LOADW(0);
    do_pass(acc0, &sw[0 * WSTRIDE], v);

    LOADW(1);
    do_pass(acc0, &sw[1 * WSTRIDE], v);
    do_pass(acc1, &sw[0 * WSTRIDE], v);

    #pragma unroll 1
    for (int s = 2; s <= 20; ++s) {
        LOADW(s);
        const float* __restrict__ w0 = &sw[s * WSTRIDE];
        do_pass(acc0, w0, v);
        do_pass(acc1, w0 - WSTRIDE, v);
        do_pass(acc2, w0 - 2 * WSTRIDE, v);
    }

    LOADW(21);
    do_pass(acc1, &sw[20 * WSTRIDE], v);
    do_pass(acc2, &sw[19 * WSTRIDE], v);

    LOADW(22);
    do_pass(acc2, &sw[20 * WSTRIDE], v);

    #undef LOADW

    float* __restrict__ o = out + (size_t)bc * (HW * HW)
                                + (size_t)(by + oy) * HW + (bx + ox);
    *(float4*)(o)              = make_float4(acc0[0], acc0[1], acc0[2], acc0[3]);
    *(float4*)(o + 4)          = make_float4(acc0[4], acc0[5], acc0[6], acc0[7]);
    *(float4*)(o + HW)         = make_float4(acc1[0], acc1[1], acc1[2], acc1[3]);
    *(float4*)(o + HW + 4)     = make_float4(acc1[4], acc1[5], acc1[6], acc1[7]);
    *(float4*)(o + 2 * HW)     = make_float4(acc2[0], acc2[1], acc2[2], acc2[3]);
    *(float4*)(o + 2 * HW + 4) = make_float4(acc2[4], acc2[5], acc2[6], acc2[7]);
}

extern "C" void kernel_launch(void* const* d_in, const int* in_sizes, int n_in,
                              void* d_out, int out_size)
{
    const float* img = (const float*)d_in[0];
    const float* wts = (const float*)d_in[1];
    if (n_in >= 2 && in_sizes[0] == 16 * KS * KS) {   // 7056 -> kernel tensor
        img = (const float*)d_in[1];
        wts = (const float*)d_in[0];
    }

    dim3 grid(HW / TILE_X, HW / TILE_Y, 16 * 3);
    blur21_kernel<<<grid, NT>>>(img, wts, (float*)d_out);
}

// round 5
// speedup vs baseline: 1.5614x; 1.0524x over previous
#include <cuda_runtime.h>

// Blur_by_Kernel: per-batch 21x21 cross-correlation, reflect pad 10.
// input (16,3,768,768) fp32, kernel (16,21,21) fp32.
// out[b,c,y,x] = sum_{ky,kx} in[b,c, refl(y+ky-10), refl(x+kx-10)] * w[b,ky,kx]
//
// R5: scalar FFMA (measured fp32 peak = 4 warp-FFMA/cyc/SM; FFMA2 measured
// half-rate -> abandoned). Row-sliding register window (28 floats) reused by
// RPT=4 output rows -> 6 windows/output-row (was 7.67). 128-thread CTAs,
// 6 CTAs/SM (24 warps, regfile-capped), branch-free interior.

namespace {
constexpr int HW   = 768;
constexpr int KS   = 21;
constexpr int PAD  = 10;
constexpr int CPT  = 8;                  // cols per thread
constexpr int RPT  = 4;                  // rows per thread
constexpr int TXN  = 16, TYN = 8;
constexpr int TILE_X = CPT * TXN;        // 128
constexpr int TILE_Y = RPT * TYN;        // 32
constexpr int SM_W = TILE_X + 2 * PAD;   // 148 floats (592B rows, 16B aligned)
constexpr int SM_H = TILE_Y + 2 * PAD;   // 52 rows
constexpr int WSTRIDE = 24;              // padded weight row (96B, 16B aligned)
constexpr int NT   = TXN * TYN;          // 128
}

// one weight-row pass: acc[j] += sum_kx v[kx+j] * w[kx]
__device__ __forceinline__ void do_pass(float (&acc)[CPT],
                                        const float* __restrict__ wr,
                                        const float (&v)[28])
{
    #pragma unroll
    for (int g = 0; g < 5; ++g) {
        const float4 w = *(const float4*)(wr + 4 * g);   // broadcast LDS.128
        #pragma unroll
        for (int j = 0; j < CPT; ++j) acc[j] = fmaf(v[4*g + 0 + j], w.x, acc[j]);
        #pragma unroll
        for (int j = 0; j < CPT; ++j) acc[j] = fmaf(v[4*g + 1 + j], w.y, acc[j]);
        #pragma unroll
        for (int j = 0; j < CPT; ++j) acc[j] = fmaf(v[4*g + 2 + j], w.z, acc[j]);
        #pragma unroll
        for (int j = 0; j < CPT; ++j) acc[j] = fmaf(v[4*g + 3 + j], w.w, acc[j]);
    }
    const float wl = wr[20];
    #pragma unroll
    for (int j = 0; j < CPT; ++j) acc[j] = fmaf(v[20 + j], wl, acc[j]);
}

__global__ __launch_bounds__(NT, 6)
void blur21_kernel(const float* __restrict__ in,
                   const float* __restrict__ wts,
                   float* __restrict__ out)
{
    __shared__ float tile[SM_H][SM_W];
    __shared__ float sw[KS * WSTRIDE];

    const int bc  = blockIdx.z;           // b*3 + c
    const int b   = bc / 3;
    const int bx  = blockIdx.x * TILE_X;
    const int by  = blockIdx.y * TILE_Y;
    const int tid = threadIdx.x;

    const float* __restrict__ img = in + (size_t)bc * (HW * HW);

    // weights for this batch, rows padded to WSTRIDE
    for (int i = tid; i < KS * WSTRIDE; i += NT) {
        const int r = i / WSTRIDE, c = i - r * WSTRIDE;
        sw[i] = (c < KS) ? wts[b * (KS * KS) + r * KS + c] : 0.f;
    }

    // input tile with reflect indexing (pad < HW -> single reflection)
    for (int i = tid; i < SM_H * SM_W; i += NT) {
        const int r  = i / SM_W;
        const int c  = i - r * SM_W;
        int gy = by + r - PAD;
        int gx = bx + c - PAD;
        gy = (gy < 0) ? -gy : ((gy >= HW) ? (2 * HW - 2 - gy) : gy);
        gx = (gx < 0) ? -gx : ((gx >= HW) ? (2 * HW - 2 - gx) : gx);
        tile[r][c] = img[gy * HW + gx];
    }
    __syncthreads();

    const int tx = tid & 15;              // 0..15
    const int ty = tid >> 4;              // 0..7
    const int ox = tx * CPT;              // 32B-aligned smem col base
    const int oy = ty * RPT;

    float acc0[CPT], acc1[CPT], acc2[CPT], acc3[CPT];
    #pragma unroll
    for (int j = 0; j < CPT; ++j) {
        acc0[j] = 0.f; acc1[j] = 0.f; acc2[j] = 0.f; acc3[j] = 0.f;
    }

    float v[28];
    #define LOADW(s)                                                     \
        do {                                                             \
            const float4* __restrict__ p =                               \
                (const float4*)&tile[oy + (s)][ox];                      \
            _Pragma("unroll")                                            \
            for (int i = 0; i < 7; ++i) {                                \
                const float4 q = p[i];                                   \
                v[4*i+0] = q.x; v[4*i+1] = q.y;                          \
                v[4*i+2] = q.z; v[4*i+3] = q.w;                          \
            }                                                            \
        } while (0)

    // window row s feeds output row r (0..3) with weight row (s - r)
    LOADW(0);
    do_pass(acc0, &sw[0 * WSTRIDE], v);

    LOADW(1);
    do_pass(acc0, &sw[1 * WSTRIDE], v);
    do_pass(acc1, &sw[0 * WSTRIDE], v);

    LOADW(2);
    do_pass(acc0, &sw[2 * WSTRIDE], v);
    do_pass(acc1, &sw[1 * WSTRIDE], v);
    do_pass(acc2, &sw[0 * WSTRIDE], v);

    #pragma unroll 1
    for (int s = 3; s <= 20; ++s) {
        LOADW(s);
        const float* __restrict__ w0 = &sw[s * WSTRIDE];
        do_pass(acc0, w0, v);
        do_pass(acc1, w0 - WSTRIDE, v);
        do_pass(acc2, w0 - 2 * WSTRIDE, v);
        do_pass(acc3, w0 - 3 * WSTRIDE, v);
    }

    LOADW(21);
    do_pass(acc1, &sw[20 * WSTRIDE], v);
    do_pass(acc2, &sw[19 * WSTRIDE], v);
    do_pass(acc3, &sw[18 * WSTRIDE], v);

    LOADW(22);
    do_pass(acc2, &sw[20 * WSTRIDE], v);
    do_pass(acc3, &sw[19 * WSTRIDE], v);

    LOADW(23);
    do_pass(acc3, &sw[20 * WSTRIDE], v);

    #undef LOADW

    float* __restrict__ o = out + (size_t)bc * (HW * HW)
                                + (size_t)(by + oy) * HW + (bx + ox);
    *(float4*)(o)              = make_float4(acc0[0], acc0[1], acc0[2], acc0[3]);
    *(float4*)(o + 4)          = make_float4(acc0[4], acc0[5], acc0[6], acc0[7]);
    *(float4*)(o + HW)         = make_float4(acc1[0], acc1[1], acc1[2], acc1[3]);
    *(float4*)(o + HW + 4)     = make_float4(acc1[4], acc1[5], acc1[6], acc1[7]);
    *(float4*)(o + 2 * HW)     = make_float4(acc2[0], acc2[1], acc2[2], acc2[3]);
    *(float4*)(o + 2 * HW + 4) = make_float4(acc2[4], acc2[5], acc2[6], acc2[7]);
    *(float4*)(o + 3 * HW)     = make_float4(acc3[0], acc3[1], acc3[2], acc3[3]);
    *(float4*)(o + 3 * HW + 4) = make_float4(acc3[4], acc3[5], acc3[6], acc3[7]);
}

extern "C" void kernel_launch(void* const* d_in, const int* in_sizes, int n_in,
                              void* d_out, int out_size)
{
    const float* img = (const float*)d_in[0];
    const float* wts = (const float*)d_in[1];
    if (n_in >= 2 && in_sizes[0] == 16 * KS * KS) {   // 7056 -> kernel tensor
        img = (const float*)d_in[1];
        wts = (const float*)d_in[0];
    }

    dim3 grid(HW / TILE_X, HW / TILE_Y, 16 * 3);
    blur21_kernel<<<grid, NT>>>(img, wts, (float*)d_out);
}